// round 5
// baseline (speedup 1.0000x reference)
#include <cuda_runtime.h>
#include <cuda_bf16.h>
#include <math.h>
#include <cstdint>

#define N_NODES 50000
#define F       128
#define NCLS    2
#define N_TILES ((N_NODES + 127) / 128)   // 391

// Scratch (device globals: allocation-free)
__device__ float g_agg[N_NODES * F];   // 25.6 MB
__device__ float g_deg[N_NODES];
__device__ int   g_is64;

// ---------------------------------------------------------------------------
// 0) index dtype probe: int64 positive values have all-odd 32b words == 0
// ---------------------------------------------------------------------------
__global__ void detect_kernel(const int* __restrict__ src,
                              const int* __restrict__ dst, int E) {
    if (threadIdx.x == 0 && blockIdx.x == 0) {
        int nz = 0;
        int lim = 2 * E < 128 ? 2 * E : 128;
        for (int i = 1; i < lim; i += 2) nz |= (src[i] | dst[i]);
        g_is64 = (nz == 0) ? 1 : 0;
    }
}

// ---------------------------------------------------------------------------
// 1) zero scratch
// ---------------------------------------------------------------------------
__global__ void zero_kernel() {
    int tid = blockIdx.x * blockDim.x + threadIdx.x;
    int stride = gridDim.x * blockDim.x;
    const int NV4 = (N_NODES * F) / 4;
    float4* agg4 = reinterpret_cast<float4*>(g_agg);
    for (int i = tid; i < NV4; i += stride)
        agg4[i] = make_float4(0.f, 0.f, 0.f, 0.f);
    for (int i = tid; i < N_NODES; i += stride)
        g_deg[i] = 0.f;
}

// ---------------------------------------------------------------------------
// 2) edge scatter: one warp per edge, vectorized f32x4 reduction into L2
// ---------------------------------------------------------------------------
__global__ void scatter_kernel(const float* __restrict__ feat,
                               const void* __restrict__ srcv,
                               const void* __restrict__ dstv,
                               int E) {
    int warp = (blockIdx.x * blockDim.x + threadIdx.x) >> 5;
    int lane = threadIdx.x & 31;
    if (warp >= E) return;

    long long s, d;
    if (g_is64) {
        s = reinterpret_cast<const long long*>(srcv)[warp];
        d = reinterpret_cast<const long long*>(dstv)[warp];
    } else {
        s = reinterpret_cast<const int*>(srcv)[warp];
        d = reinterpret_cast<const int*>(dstv)[warp];
    }
    if (s < 0 || s >= N_NODES || d < 0 || d >= N_NODES) return;

    float4 v = *reinterpret_cast<const float4*>(&feat[(size_t)s * F + lane * 4]);
    float* addr = &g_agg[(size_t)d * F + lane * 4];
    asm volatile("red.global.add.v4.f32 [%0], {%1, %2, %3, %4};"
                 :: "l"(addr), "f"(v.x), "f"(v.y), "f"(v.z), "f"(v.w)
                 : "memory");
    if (lane == 0) atomicAdd(&g_deg[d], 1.0f);
}

// ---------------------------------------------------------------------------
// 2b) scale g_agg rows by 1/max(deg,1) so GEMM can cp.async it raw
// ---------------------------------------------------------------------------
__global__ void scale_kernel() {
    int tid = blockIdx.x * blockDim.x + threadIdx.x;
    int stride = gridDim.x * blockDim.x;
    const int NV4 = N_NODES * (F / 4);
    float4* a4 = reinterpret_cast<float4*>(g_agg);
    for (int i = tid; i < NV4; i += stride) {
        int node = i >> 5;
        float invd = __fdividef(1.0f, fmaxf(g_deg[node], 1.0f));
        float4 v = a4[i];
        v.x *= invd; v.y *= invd; v.z *= invd; v.w *= invd;
        a4[i] = v;
    }
}

// ---------------------------------------------------------------------------
// 3) tf32 mma.sync GEMM: D[128tile x 128] = [X | Agg] @ [Ws | Wn]^T
//    512 threads, cp.async double-buffered A staging, fused epilogue
// ---------------------------------------------------------------------------
#define A_PAD    36                      // floats per A row (144 B, 16B-aligned)
#define B_PAD    132                     // floats per B(k) row
#define OFF_B    0                       // [256][132] f32 = 135168 B
#define OFF_A    135168                  // 2 x [128][36] f32 = 36864 B
#define OFF_BN   172032
#define OFF_F0   172544
#define OFF_F1   173056
#define OFF_PART 173568                  // [128][4][2] f32 = 4096 B
#define SMEM_TOTAL 177664

__device__ __forceinline__ uint32_t smem_u32(const void* p) {
    uint32_t a;
    asm("{ .reg .u64 t; cvta.to.shared.u64 t, %1; cvt.u32.u64 %0, t; }"
        : "=r"(a) : "l"(p));
    return a;
}
__device__ __forceinline__ void mma_tf32(float* c, const uint32_t* a,
                                         const uint32_t* b) {
    asm volatile("mma.sync.aligned.m16n8k8.row.col.f32.tf32.tf32.f32 "
                 "{%0,%1,%2,%3}, {%4,%5,%6,%7}, {%8,%9}, {%0,%1,%2,%3};"
                 : "+f"(c[0]), "+f"(c[1]), "+f"(c[2]), "+f"(c[3])
                 : "r"(a[0]), "r"(a[1]), "r"(a[2]), "r"(a[3]),
                   "r"(b[0]), "r"(b[1]));
}
#define CP_ASYNC16(dst, src) \
    asm volatile("cp.async.cg.shared.global [%0], [%1], 16;" \
                 :: "r"(dst), "l"(src) : "memory")
#define CP_COMMIT() asm volatile("cp.async.commit_group;" ::: "memory")
#define CP_WAIT1()  asm volatile("cp.async.wait_group 1;" ::: "memory")
#define CP_WAIT0()  asm volatile("cp.async.wait_group 0;" ::: "memory")

__global__ void __launch_bounds__(512, 1)
mma_gemm_kernel(const float* __restrict__ feat,
                const float* __restrict__ Wself,
                const float* __restrict__ Wneigh,
                const float* __restrict__ bneigh,
                const float* __restrict__ Wfc,
                const float* __restrict__ bfc,
                float* __restrict__ out) {
    extern __shared__ char smem[];
    uint32_t* Bs = (uint32_t*)(smem + OFF_B);
    float* bn_s  = (float*)(smem + OFF_BN);
    float* f0_s  = (float*)(smem + OFF_F0);
    float* f1_s  = (float*)(smem + OFF_F1);
    float* part  = (float*)(smem + OFF_PART);
    const uint32_t sA = smem_u32(smem) + OFF_A;

    const int tid = threadIdx.x;
    const int wid = tid >> 5, lane = tid & 31;
    const int m_idx = wid >> 2;          // 0..3: rows m_idx*32..+32
    const int n_idx = wid & 3;           // 0..3: cols n_idx*32..+32
    const int groupr = lane >> 2, tcol = lane & 3;

    // --- stage B = [Ws | Wn]^T as [k][n] raw f32, once per CTA --------------
    const float4* Ws4 = (const float4*)Wself;
    const float4* Wn4 = (const float4*)Wneigh;
    for (int t = tid; t < 128 * 64; t += 512) {
        int j  = t & 127;                 // output col n
        int kq = t >> 7;                  // float4 along combined K
        float4 v = (kq < 32) ? Ws4[j * 32 + kq] : Wn4[j * 32 + (kq - 32)];
        int k = kq * 4;
        Bs[(k + 0) * B_PAD + j] = __float_as_uint(v.x);
        Bs[(k + 1) * B_PAD + j] = __float_as_uint(v.y);
        Bs[(k + 2) * B_PAD + j] = __float_as_uint(v.z);
        Bs[(k + 3) * B_PAD + j] = __float_as_uint(v.w);
    }
    if (tid < 128) {
        bn_s[tid] = bneigh[tid];
        f0_s[tid] = Wfc[tid];
        f1_s[tid] = Wfc[128 + tid];
    }

    const char* featb = (const char*)feat;
    const char* aggb  = (const char*)g_agg;
    const float bfc0 = bfc[0], bfc1 = bfc[1];

    for (int tile = blockIdx.x; tile < N_TILES; tile += gridDim.x) {

        // cp.async stager: chunk c (32 floats of K) into buffer buf
        auto stage = [&](int c, int buf) {
            const char* base = (c < 4) ? featb : aggb;
            int koff = (c & 3) * 128;                 // byte offset in row
            #pragma unroll
            for (int i = 0; i < 2; i++) {
                int idx = tid + i * 512;              // 0..1023
                int row = idx >> 3, q = idx & 7;
                int node = tile * 128 + row;
                if (node >= N_NODES) node = N_NODES - 1;
                const char* src = base + (size_t)node * 512 + koff + q * 16;
                uint32_t dst = sA + buf * (128 * A_PAD * 4) + row * (A_PAD * 4) + q * 16;
                CP_ASYNC16(dst, src);
            }
        };

        float C[2][4][4];
        #pragma unroll
        for (int mt = 0; mt < 2; mt++)
            #pragma unroll
            for (int nt = 0; nt < 4; nt++)
                #pragma unroll
                for (int i = 0; i < 4; i++) C[mt][nt][i] = 0.f;

        stage(0, 0);
        CP_COMMIT();

        #pragma unroll 1
        for (int c = 0; c < 8; c++) {
            if (c < 7) { stage(c + 1, (c + 1) & 1); CP_COMMIT(); CP_WAIT1(); }
            else       { CP_WAIT0(); }
            __syncthreads();

            const uint32_t* A_ = (const uint32_t*)(smem + OFF_A) +
                                 (c & 1) * (128 * A_PAD);
            const int abase = (m_idx * 32 + groupr) * A_PAD;
            const int bcol  = n_idx * 32 + groupr;
            #pragma unroll
            for (int kk = 0; kk < 4; kk++) {
                const int ka = kk * 8 + tcol;
                uint32_t a[2][4];
                #pragma unroll
                for (int mt = 0; mt < 2; mt++) {
                    int ab = abase + mt * 16 * A_PAD;
                    a[mt][0] = A_[ab + ka];
                    a[mt][1] = A_[ab + 8 * A_PAD + ka];
                    a[mt][2] = A_[ab + ka + 4];
                    a[mt][3] = A_[ab + 8 * A_PAD + ka + 4];
                }
                const int kb = (c * 32 + kk * 8 + tcol) * B_PAD;
                #pragma unroll
                for (int nt = 0; nt < 4; nt++) {
                    uint32_t b[2];
                    b[0] = Bs[kb + bcol + nt * 8];
                    b[1] = Bs[kb + 4 * B_PAD + bcol + nt * 8];
                    mma_tf32(C[0][nt], a[0], b);
                    mma_tf32(C[1][nt], a[1], b);
                }
            }
            __syncthreads();
        }

        // --- epilogue: h = relu(c + bn); p += h * fc; quad-reduce ----------
        float p[2][2][2];   // [mt][rowhalf][cls]
        #pragma unroll
        for (int mt = 0; mt < 2; mt++)
            #pragma unroll
            for (int hh = 0; hh < 2; hh++) { p[mt][hh][0] = 0.f; p[mt][hh][1] = 0.f; }

        #pragma unroll
        for (int nt = 0; nt < 4; nt++) {
            #pragma unroll
            for (int ii = 0; ii < 2; ii++) {
                int col = n_idx * 32 + nt * 8 + 2 * tcol + ii;
                float bnv = bn_s[col], f0v = f0_s[col], f1v = f1_s[col];
                #pragma unroll
                for (int mt = 0; mt < 2; mt++) {
                    #pragma unroll
                    for (int hh = 0; hh < 2; hh++) {
                        float h = fmaxf(C[mt][nt][hh * 2 + ii] + bnv, 0.f);
                        p[mt][hh][0] += h * f0v;
                        p[mt][hh][1] += h * f1v;
                    }
                }
            }
        }
        #pragma unroll
        for (int mt = 0; mt < 2; mt++)
            #pragma unroll
            for (int hh = 0; hh < 2; hh++)
                #pragma unroll
                for (int cl = 0; cl < 2; cl++) {
                    float v = p[mt][hh][cl];
                    v += __shfl_xor_sync(0xffffffffu, v, 1);
                    v += __shfl_xor_sync(0xffffffffu, v, 2);
                    p[mt][hh][cl] = v;
                }
        if (tcol == 0) {
            #pragma unroll
            for (int mt = 0; mt < 2; mt++)
                #pragma unroll
                for (int hh = 0; hh < 2; hh++) {
                    int row = m_idx * 32 + mt * 16 + hh * 8 + groupr;
                    part[row * 8 + n_idx * 2 + 0] = p[mt][hh][0];
                    part[row * 8 + n_idx * 2 + 1] = p[mt][hh][1];
                }
        }
        __syncthreads();
        if (tid < 128) {
            int node = tile * 128 + tid;
            if (node < N_NODES) {
                float l0 = part[tid * 8 + 0] + part[tid * 8 + 2] +
                           part[tid * 8 + 4] + part[tid * 8 + 6] + bfc0;
                float l1 = part[tid * 8 + 1] + part[tid * 8 + 3] +
                           part[tid * 8 + 5] + part[tid * 8 + 7] + bfc1;
                float2 o;
                o.x = 1.0f / (1.0f + expf(-l0));
                o.y = 1.0f / (1.0f + expf(-l1));
                *(float2*)&out[(size_t)node * 2] = o;
            }
        }
        __syncthreads();
    }
}

// ---------------------------------------------------------------------------
extern "C" void kernel_launch(void* const* d_in, const int* in_sizes, int n_in,
                              void* d_out, int out_size) {
    const float* feat   = (const float*)d_in[0];
    const void*  src    = d_in[1];
    const void*  dst    = d_in[2];
    const float* Wself  = (const float*)d_in[3];
    const float* Wneigh = (const float*)d_in[4];
    const float* bneigh = (const float*)d_in[5];
    const float* Wfc    = (const float*)d_in[6];
    const float* bfc    = (const float*)d_in[7];
    float*       out    = (float*)d_out;
    int E = in_sizes[1];

    cudaFuncSetAttribute(mma_gemm_kernel,
                         cudaFuncAttributeMaxDynamicSharedMemorySize, SMEM_TOTAL);

    detect_kernel<<<1, 32>>>((const int*)src, (const int*)dst, E);
    zero_kernel<<<1024, 256>>>();

    int sblocks = (E + 7) / 8;   // 8 edges (warps) per 256-thread block
    scatter_kernel<<<sblocks, 256>>>(feat, src, dst, E);

    scale_kernel<<<1024, 256>>>();

    mma_gemm_kernel<<<148, 512, SMEM_TOTAL>>>(
        feat, Wself, Wneigh, bneigh, Wfc, bfc, out);
}